// round 4
// baseline (speedup 1.0000x reference)
#include <cuda_runtime.h>

#define NN 64
#define CC 128
#define FF 2048
#define MM 128

__device__ float g_W[(size_t)NN * CC * MM];  // softmax weights scratch [n][c][m]

typedef unsigned long long u64;

__device__ __forceinline__ u64 ffma2(u64 a, u64 b, u64 c) {
    u64 d;
    asm("fma.rn.f32x2 %0, %1, %2, %3;" : "=l"(d) : "l"(a), "l"(b), "l"(c));
    return d;
}
__device__ __forceinline__ u64 pack2(float x, float y) {
    u64 d;
    asm("mov.b64 %0, {%1, %2};" : "=l"(d) : "f"(x), "f"(y));
    return d;
}
__device__ __forceinline__ float2 unpack2(u64 v) {
    float2 r;
    asm("mov.b64 {%0, %1}, %2;" : "=f"(r.x), "=f"(r.y) : "l"(v));
    return r;
}

// ============================================================================
// Kernel 1: S[n,m] = sum_f X[n,c,f]*A[c,m,f], one block per c, fused softmax
// over m, writes W to g_W[n][c][m]. Tile 64n x 128m, K chunk 32, f32x2 pairs
// over K. smem XOR-swizzled so the k-major->pair-major transpose and the
// operand reads are (nearly) conflict-free.
// ============================================================================
__global__ __launch_bounds__(256) void k1_scores(const float* __restrict__ X,
                                                 const float* __restrict__ A) {
    const int c   = blockIdx.x;
    const int tid = threadIdx.x;
    const int tx  = tid & 15;   // m group
    const int ty  = tid >> 4;   // n group

    __shared__ __align__(16) float sm[64 * 132];      // 33.8 KB (epilogue view)
    u64*    as2  = reinterpret_cast<u64*>(sm);        // [16 kp][128 m]
    u64*    xs2  = reinterpret_cast<u64*>(sm + 4096); // [16 kp][64 n]
    float2* as2f = reinterpret_cast<float2*>(sm);
    float2* xs2f = reinterpret_cast<float2*>(sm + 4096);

    const float* Ab = A + (size_t)c * MM * FF;

    u64 acc[4][8];
#pragma unroll
    for (int i = 0; i < 4; i++)
#pragma unroll
        for (int j = 0; j < 8; j++) acc[i][j] = 0ull;

    float4 ra[4], rx[2];
    // prefetch chunk 0
#pragma unroll
    for (int it = 0; it < 4; it++) {
        int idx = it * 256 + tid, m = idx >> 3, q = idx & 7;
        ra[it] = *reinterpret_cast<const float4*>(Ab + (size_t)m * FF + q * 4);
    }
#pragma unroll
    for (int it = 0; it < 2; it++) {
        int idx = it * 256 + tid, n = idx >> 3, q = idx & 7;
        rx[it] = *reinterpret_cast<const float4*>(X + ((size_t)n * CC + c) * FF + q * 4);
    }

    for (int ch = 0; ch < 64; ch++) {
        // stage registers -> smem (k-pair major, XOR swizzle)
#pragma unroll
        for (int it = 0; it < 4; it++) {
            int idx = it * 256 + tid, m = idx >> 3, q = idx & 7;
            int kp = q * 2;
            as2f[kp * 128 + (m ^ kp)]             = make_float2(ra[it].x, ra[it].y);
            as2f[(kp + 1) * 128 + (m ^ (kp + 1))] = make_float2(ra[it].z, ra[it].w);
        }
#pragma unroll
        for (int it = 0; it < 2; it++) {
            int idx = it * 256 + tid, n = idx >> 3, q = idx & 7;
            int kp = q * 2;
            xs2f[kp * 64 + (n ^ kp)]              = make_float2(rx[it].x, rx[it].y);
            xs2f[(kp + 1) * 64 + (n ^ (kp + 1))]  = make_float2(rx[it].z, rx[it].w);
        }
        __syncthreads();

        if (ch < 63) {  // prefetch next chunk while computing
            const int k0 = (ch + 1) * 32;
#pragma unroll
            for (int it = 0; it < 4; it++) {
                int idx = it * 256 + tid, m = idx >> 3, q = idx & 7;
                ra[it] = *reinterpret_cast<const float4*>(Ab + (size_t)m * FF + k0 + q * 4);
            }
#pragma unroll
            for (int it = 0; it < 2; it++) {
                int idx = it * 256 + tid, n = idx >> 3, q = idx & 7;
                rx[it] = *reinterpret_cast<const float4*>(X + ((size_t)n * CC + c) * FF + k0 + q * 4);
            }
        }

#pragma unroll 4
        for (int kp = 0; kp < 16; kp++) {
            u64 a2[8], x2[4];
#pragma unroll
            for (int j = 0; j < 8; j++) a2[j] = as2[kp * 128 + ((j * 16 + tx) ^ kp)];
#pragma unroll
            for (int i = 0; i < 4; i++) x2[i] = xs2[kp * 64 + ((ty * 4 + i) ^ kp)];
#pragma unroll
            for (int i = 0; i < 4; i++)
#pragma unroll
                for (int j = 0; j < 8; j++) acc[i][j] = ffma2(x2[i], a2[j], acc[i][j]);
        }
        __syncthreads();
    }

    // epilogue: reduce pair halves, stash scores, softmax over m, write g_W
    float* Ss = sm;  // [64][132]
#pragma unroll
    for (int i = 0; i < 4; i++) {
        int n = ty * 4 + i;
#pragma unroll
        for (int j = 0; j < 8; j++) {
            float2 v = unpack2(acc[i][j]);
            Ss[n * 132 + (j * 16 + tx)] = v.x + v.y;
        }
    }
    __syncthreads();

    if (tid < 64) {
        float* row = Ss + tid * 132;
        float mx = row[0];
#pragma unroll 8
        for (int m = 1; m < 128; m++) mx = fmaxf(mx, row[m]);
        float sum = 0.f;
#pragma unroll 8
        for (int m = 0; m < 128; m++) {
            float e = __expf(row[m] - mx);
            sum += e;
            row[m] = e;
        }
        float inv = 1.f / sum;
        float4* w4 = reinterpret_cast<float4*>(g_W + ((size_t)tid * CC + c) * MM);
#pragma unroll 8
        for (int m4 = 0; m4 < 32; m4++) {
            w4[m4] = make_float4(row[m4 * 4 + 0] * inv, row[m4 * 4 + 1] * inv,
                                 row[m4 * 4 + 2] * inv, row[m4 * 4 + 3] * inv);
        }
    }
}

// ============================================================================
// Kernel 2: out[n,c,f] = sum_m W[n,c,m]*X[n,m,f]. Grid (16 f-tiles, 64 n).
// Tile 128c x 128f, K=m chunked by 32. W transposed to smem [m][c] (pad 129),
// X natural [m][f]. Thread tile 8c x 8f as 4 f32x2 pairs over f.
// ============================================================================
__global__ __launch_bounds__(256, 2) void k2_combine(const float* __restrict__ X,
                                                     float* __restrict__ Out) {
    const int n   = blockIdx.y;
    const int f0  = blockIdx.x * 128;
    const int tid = threadIdx.x;
    const int tx  = tid & 15;   // f
    const int ty  = tid >> 4;   // c

    __shared__ __align__(16) float Wt[32 * 129];  // [m][c] padded
    __shared__ __align__(16) float Xs[32 * 128];  // [m][f]
    u64* Xs8 = reinterpret_cast<u64*>(Xs);

    const float* Wg = g_W + (size_t)n * CC * MM;
    const float* Xb = X + (size_t)n * CC * FF + f0;

    u64 acc[8][4];
#pragma unroll
    for (int i = 0; i < 8; i++)
#pragma unroll
        for (int p = 0; p < 4; p++) acc[i][p] = 0ull;

    float4 rw[4], rx[4];
    // prefetch chunk 0
#pragma unroll
    for (int it = 0; it < 4; it++) {
        int idx = it * 256 + tid, cc = idx >> 3, q = idx & 7;
        rw[it] = *reinterpret_cast<const float4*>(Wg + (size_t)cc * MM + q * 4);
    }
#pragma unroll
    for (int it = 0; it < 4; it++) {
        int idx = it * 256 + tid, ml = idx >> 5, fq = idx & 31;
        rx[it] = *reinterpret_cast<const float4*>(Xb + (size_t)ml * FF + fq * 4);
    }

    for (int ch = 0; ch < 4; ch++) {
#pragma unroll
        for (int it = 0; it < 4; it++) {
            int idx = it * 256 + tid, cc = idx >> 3, q = idx & 7;
            Wt[(q * 4 + 0) * 129 + cc] = rw[it].x;
            Wt[(q * 4 + 1) * 129 + cc] = rw[it].y;
            Wt[(q * 4 + 2) * 129 + cc] = rw[it].z;
            Wt[(q * 4 + 3) * 129 + cc] = rw[it].w;
        }
#pragma unroll
        for (int it = 0; it < 4; it++) {
            int idx = it * 256 + tid, ml = idx >> 5, fq = idx & 31;
            *reinterpret_cast<float4*>(Xs + ml * 128 + fq * 4) = rx[it];
        }
        __syncthreads();

        if (ch < 3) {
            const int m0 = (ch + 1) * 32;
#pragma unroll
            for (int it = 0; it < 4; it++) {
                int idx = it * 256 + tid, cc = idx >> 3, q = idx & 7;
                rw[it] = *reinterpret_cast<const float4*>(Wg + (size_t)cc * MM + m0 + q * 4);
            }
#pragma unroll
            for (int it = 0; it < 4; it++) {
                int idx = it * 256 + tid, ml = idx >> 5, fq = idx & 31;
                rx[it] = *reinterpret_cast<const float4*>(Xb + (size_t)(m0 + ml) * FF + fq * 4);
            }
        }

#pragma unroll 8
        for (int k = 0; k < 32; k++) {
            u64 wdup[8], x2[4];
#pragma unroll
            for (int ci = 0; ci < 8; ci++) {
                float w = Wt[k * 129 + ty * 8 + ci];
                wdup[ci] = pack2(w, w);
            }
#pragma unroll
            for (int fp = 0; fp < 4; fp++) x2[fp] = Xs8[k * 64 + fp * 16 + tx];
#pragma unroll
            for (int ci = 0; ci < 8; ci++)
#pragma unroll
                for (int fp = 0; fp < 4; fp++)
                    acc[ci][fp] = ffma2(wdup[ci], x2[fp], acc[ci][fp]);
        }
        __syncthreads();
    }

    // store: thread owns c = ty*8+ci, f-pairs at 2*(fp*16+tx)
#pragma unroll
    for (int ci = 0; ci < 8; ci++) {
        int c = ty * 8 + ci;
        u64* Outp = reinterpret_cast<u64*>(Out + ((size_t)n * CC + c) * FF + f0);
#pragma unroll
        for (int fp = 0; fp < 4; fp++) Outp[fp * 16 + tx] = acc[ci][fp];
    }
}

extern "C" void kernel_launch(void* const* d_in, const int* in_sizes, int n_in,
                              void* d_out, int out_size) {
    const float* X = (const float*)d_in[0];
    const float* A = (const float*)d_in[1];
    float* Out = (float*)d_out;

    k1_scores<<<CC, 256>>>(X, A);
    dim3 g2(FF / 128, NN);
    k2_combine<<<g2, 256>>>(X, Out);
}

// round 5
// speedup vs baseline: 1.2137x; 1.2137x over previous
#include <cuda_runtime.h>

#define NN 64
#define CC 128
#define FF 2048
#define MM 128

__device__ float g_W[(size_t)NN * CC * MM];  // softmax weights scratch [n][c][m]

typedef unsigned long long u64;

__device__ __forceinline__ u64 ffma2(u64 a, u64 b, u64 c) {
    u64 d;
    asm("fma.rn.f32x2 %0, %1, %2, %3;" : "=l"(d) : "l"(a), "l"(b), "l"(c));
    return d;
}
__device__ __forceinline__ u64 pack2(float x, float y) {
    u64 d;
    asm("mov.b64 %0, {%1, %2};" : "=l"(d) : "f"(x), "f"(y));
    return d;
}
__device__ __forceinline__ float2 unpack2(u64 v) {
    float2 r;
    asm("mov.b64 {%0, %1}, %2;" : "=f"(r.x), "=f"(r.y) : "l"(v));
    return r;
}

// ============================================================================
// Kernel 1: S[n,m] = sum_f X[n,c,f]*A[c,m,f], one block per c, fused softmax.
// smem tiles hold float4 chunks of 4 consecutive k: as4[q][m], xs4[q][n],
// q = k/4 within a 32-k chunk. Swizzle index^q keeps stores conflict-free
// while all read-side XORs fold into precomputed registers + immediates.
// Thread tile 4n x 8m, pair-over-K accumulators (u64), LDS.128 operands.
// ============================================================================
__global__ __launch_bounds__(256) void k1_scores(const float* __restrict__ X,
                                                 const float* __restrict__ A) {
    const int c   = blockIdx.x;
    const int tid = threadIdx.x;
    const int tx  = tid & 15;   // m: j*16+tx
    const int ty  = tid >> 4;   // n: ty*4+i

    __shared__ __align__(16) float sm[64 * 132];   // 33.8 KB; tiles use 24 KB
    float4*     as4   = reinterpret_cast<float4*>(sm);            // [8 q][128 m]
    float4*     xs4   = reinterpret_cast<float4*>(sm + 4096);     // [8 q][64 n]
    ulonglong2* as4u  = reinterpret_cast<ulonglong2*>(sm);
    ulonglong2* xs4u  = reinterpret_cast<ulonglong2*>(sm + 4096);

    const float* Ab = A + (size_t)c * MM * FF;

    // precompute swizzled lane offsets: a-side tx^q, x-side (ty*4)^(q&4)
    int txq[8];
#pragma unroll
    for (int q = 0; q < 8; q++) txq[q] = tx ^ q;
    int tyq[2];
    tyq[0] = ty * 4;
    tyq[1] = (ty * 4) ^ 4;

    u64 acc[4][8];
#pragma unroll
    for (int i = 0; i < 4; i++)
#pragma unroll
        for (int j = 0; j < 8; j++) acc[i][j] = 0ull;

    float4 ra[4], rx[2];
    // prefetch chunk 0
#pragma unroll
    for (int it = 0; it < 4; it++) {
        int idx = it * 256 + tid, m = idx >> 3, q = idx & 7;
        ra[it] = *reinterpret_cast<const float4*>(Ab + (size_t)m * FF + q * 4);
    }
#pragma unroll
    for (int it = 0; it < 2; it++) {
        int idx = it * 256 + tid, n = idx >> 3, q = idx & 7;
        rx[it] = *reinterpret_cast<const float4*>(X + ((size_t)n * CC + c) * FF + q * 4);
    }

    for (int ch = 0; ch < 64; ch++) {
        // stage registers -> smem (swizzle: column index XOR q)
#pragma unroll
        for (int it = 0; it < 4; it++) {
            int idx = it * 256 + tid, m = idx >> 3, q = idx & 7;
            as4[q * 128 + (m ^ q)] = ra[it];
        }
#pragma unroll
        for (int it = 0; it < 2; it++) {
            int idx = it * 256 + tid, n = idx >> 3, q = idx & 7;
            xs4[q * 64 + (n ^ q)] = rx[it];
        }
        __syncthreads();

        if (ch < 63) {  // prefetch next chunk during compute
            const int k0 = (ch + 1) * 32;
#pragma unroll
            for (int it = 0; it < 4; it++) {
                int idx = it * 256 + tid, m = idx >> 3, q = idx & 7;
                ra[it] = *reinterpret_cast<const float4*>(Ab + (size_t)m * FF + k0 + q * 4);
            }
#pragma unroll
            for (int it = 0; it < 2; it++) {
                int idx = it * 256 + tid, n = idx >> 3, q = idx & 7;
                rx[it] = *reinterpret_cast<const float4*>(X + ((size_t)n * CC + c) * FF + k0 + q * 4);
            }
        }

#pragma unroll
        for (int q = 0; q < 8; q++) {
            // read addresses: all XOR terms are immediates or precomputed regs
            ulonglong2 x2[4], a2[8];
#pragma unroll
            for (int i = 0; i < 4; i++)
                x2[i] = xs4u[q * 64 + tyq[(q >> 2) & 1] + (i ^ (q & 3))];
#pragma unroll
            for (int j = 0; j < 8; j++)
                a2[j] = as4u[q * 128 + j * 16 + txq[q]];
#pragma unroll
            for (int i = 0; i < 4; i++)
#pragma unroll
                for (int j = 0; j < 8; j++) {
                    acc[i][j] = ffma2(x2[i].x, a2[j].x, acc[i][j]);
                    acc[i][j] = ffma2(x2[i].y, a2[j].y, acc[i][j]);
                }
        }
        __syncthreads();
    }

    // epilogue: reduce pair halves, stash scores, softmax over m, write g_W
    float* Ss = sm;  // [64][132]
#pragma unroll
    for (int i = 0; i < 4; i++) {
        int n = ty * 4 + i;
#pragma unroll
        for (int j = 0; j < 8; j++) {
            float2 v = unpack2(acc[i][j]);
            Ss[n * 132 + (j * 16 + tx)] = v.x + v.y;
        }
    }
    __syncthreads();

    if (tid < 64) {
        float* row = Ss + tid * 132;
        float mx = row[0];
#pragma unroll 8
        for (int m = 1; m < 128; m++) mx = fmaxf(mx, row[m]);
        float sum = 0.f;
#pragma unroll 8
        for (int m = 0; m < 128; m++) {
            float e = __expf(row[m] - mx);
            sum += e;
            row[m] = e;
        }
        float inv = 1.f / sum;
        float4* w4 = reinterpret_cast<float4*>(g_W + ((size_t)tid * CC + c) * MM);
#pragma unroll 8
        for (int m4 = 0; m4 < 32; m4++) {
            w4[m4] = make_float4(row[m4 * 4 + 0] * inv, row[m4 * 4 + 1] * inv,
                                 row[m4 * 4 + 2] * inv, row[m4 * 4 + 3] * inv);
        }
    }
}

// ============================================================================
// Kernel 2: out[n,c,f] = sum_m W[n,c,m]*X[n,m,f]. Grid (16 f-tiles, 64 n).
// Tile 128c x 128f, K=m chunked by 32.
// Wt smem [m][c] pitch 132 (16B-aligned rows). W staged with c on the lane
// index -> conflict-free transpose stores; reads are 2 broadcast LDS.128/k.
// Xs [m][f] natural, reads 2 LDS.128/k. Thread tile 8c x 8f (f32x2 f-pairs).
// ============================================================================
__global__ __launch_bounds__(256, 2) void k2_combine(const float* __restrict__ X,
                                                     float* __restrict__ Out) {
    const int n   = blockIdx.y;
    const int f0  = blockIdx.x * 128;
    const int tid = threadIdx.x;
    const int tx  = tid & 15;   // f (float4 column)
    const int ty  = tid >> 4;   // c group

    __shared__ __align__(16) float Wt[32 * 132];  // [m][c], pitch 132 floats
    __shared__ __align__(16) float Xs[32 * 128];  // [m][f]
    float4*     Wt4  = reinterpret_cast<float4*>(Wt);  // pitch 33 float4
    float4*     Xs4  = reinterpret_cast<float4*>(Xs);  // pitch 32 float4
    ulonglong2* Xs4u = reinterpret_cast<ulonglong2*>(Xs);

    const float* Wg = g_W + (size_t)n * CC * MM;
    const float* Xb = X + (size_t)n * CC * FF + f0;

    ulonglong2 acc2[8][2];
#pragma unroll
    for (int i = 0; i < 8; i++)
#pragma unroll
        for (int h = 0; h < 2; h++) acc2[i][h] = make_ulonglong2(0ull, 0ull);

    float4 rw[4], rx[4];
    // prefetch chunk 0: W with c on the lane index (strided global, L2-hot)
#pragma unroll
    for (int it = 0; it < 4; it++) {
        int idx = it * 256 + tid, cc = idx & 127, q = idx >> 7;
        rw[it] = *reinterpret_cast<const float4*>(Wg + (size_t)cc * MM + q * 4);
    }
#pragma unroll
    for (int it = 0; it < 4; it++) {
        int idx = it * 256 + tid, ml = idx >> 5, fq = idx & 31;
        rx[it] = *reinterpret_cast<const float4*>(Xb + (size_t)ml * FF + fq * 4);
    }

    for (int ch = 0; ch < 4; ch++) {
#pragma unroll
        for (int it = 0; it < 4; it++) {
            int idx = it * 256 + tid, cc = idx & 127, q = idx >> 7;
            Wt[(q * 4 + 0) * 132 + cc] = rw[it].x;   // lanes: cc consecutive
            Wt[(q * 4 + 1) * 132 + cc] = rw[it].y;   // -> conflict-free
            Wt[(q * 4 + 2) * 132 + cc] = rw[it].z;
            Wt[(q * 4 + 3) * 132 + cc] = rw[it].w;
        }
#pragma unroll
        for (int it = 0; it < 4; it++) {
            int idx = it * 256 + tid, ml = idx >> 5, fq = idx & 31;
            Xs4[ml * 32 + fq] = rx[it];
        }
        __syncthreads();

        if (ch < 3) {
            const int m0 = (ch + 1) * 32;
#pragma unroll
            for (int it = 0; it < 4; it++) {
                int idx = it * 256 + tid, cc = idx & 127, q = idx >> 7;
                rw[it] = *reinterpret_cast<const float4*>(Wg + (size_t)cc * MM + m0 + q * 4);
            }
#pragma unroll
            for (int it = 0; it < 4; it++) {
                int idx = it * 256 + tid, ml = idx >> 5, fq = idx & 31;
                rx[it] = *reinterpret_cast<const float4*>(Xb + (size_t)(m0 + ml) * FF + fq * 4);
            }
        }

#pragma unroll 4
        for (int k = 0; k < 32; k++) {
            float4 w40 = Wt4[k * 33 + ty * 2];        // c = ty*8 .. +3 (broadcast)
            float4 w41 = Wt4[k * 33 + ty * 2 + 1];    // c = ty*8+4 .. +7
            ulonglong2 xa = Xs4u[k * 32 + tx];        // f-pairs 2tx*2 ..
            ulonglong2 xb = Xs4u[k * 32 + 16 + tx];
            u64 wd[8];
            wd[0] = pack2(w40.x, w40.x); wd[1] = pack2(w40.y, w40.y);
            wd[2] = pack2(w40.z, w40.z); wd[3] = pack2(w40.w, w40.w);
            wd[4] = pack2(w41.x, w41.x); wd[5] = pack2(w41.y, w41.y);
            wd[6] = pack2(w41.z, w41.z); wd[7] = pack2(w41.w, w41.w);
#pragma unroll
            for (int ci = 0; ci < 8; ci++) {
                acc2[ci][0].x = ffma2(wd[ci], xa.x, acc2[ci][0].x);
                acc2[ci][0].y = ffma2(wd[ci], xa.y, acc2[ci][0].y);
                acc2[ci][1].x = ffma2(wd[ci], xb.x, acc2[ci][1].x);
                acc2[ci][1].y = ffma2(wd[ci], xb.y, acc2[ci][1].y);
            }
        }
        __syncthreads();
    }

    // store: thread owns c = ty*8+ci; float4 columns h*16+tx (same map as Xs)
#pragma unroll
    for (int ci = 0; ci < 8; ci++) {
        int c = ty * 8 + ci;
        float4* O4 = reinterpret_cast<float4*>(Out + ((size_t)n * CC + c) * FF + f0);
        O4[tx]      = *reinterpret_cast<float4*>(&acc2[ci][0]);
        O4[16 + tx] = *reinterpret_cast<float4*>(&acc2[ci][1]);
    }
}

extern "C" void kernel_launch(void* const* d_in, const int* in_sizes, int n_in,
                              void* d_out, int out_size) {
    const float* X = (const float*)d_in[0];
    const float* A = (const float*)d_in[1];
    float* Out = (float*)d_out;

    k1_scores<<<CC, 256>>>(X, A);
    dim3 g2(FF / 128, NN);
    k2_combine<<<g2, 256>>>(X, Out);
}

// round 6
// speedup vs baseline: 1.2162x; 1.0020x over previous
#include <cuda_runtime.h>

#define NN 64
#define CC 128
#define FF 2048
#define MM 128

__device__ float g_W[(size_t)NN * CC * MM];  // softmax weights scratch [n][c][m]

typedef unsigned long long u64;

__device__ __forceinline__ u64 ffma2(u64 a, u64 b, u64 c) {
    u64 d;
    asm("fma.rn.f32x2 %0, %1, %2, %3;" : "=l"(d) : "l"(a), "l"(b), "l"(c));
    return d;
}
__device__ __forceinline__ u64 pack2(float x, float y) {
    u64 d;
    asm("mov.b64 %0, {%1, %2};" : "=l"(d) : "f"(x), "f"(y));
    return d;
}
__device__ __forceinline__ float2 unpack2(u64 v) {
    float2 r;
    asm("mov.b64 {%0, %1}, %2;" : "=f"(r.x), "=f"(r.y) : "l"(v));
    return r;
}

// ============================================================================
// Kernel 1: S[n,m] = sum_f X[n,c,f]*A[c,m,f], one block per c, fused softmax.
// smem tiles hold float4 chunks of 4 consecutive k: as4[q][m], xs4[q][n],
// q = k/4 within a 32-k chunk. Swizzle index^q keeps stores conflict-free
// while all read-side XORs fold into precomputed registers + immediates.
// Thread tile 4n x 8m, pair-over-K accumulators (u64), LDS.128 operands.
// ============================================================================
__global__ __launch_bounds__(256) void k1_scores(const float* __restrict__ X,
                                                 const float* __restrict__ A) {
    const int c   = blockIdx.x;
    const int tid = threadIdx.x;
    const int tx  = tid & 15;   // m: j*16+tx
    const int ty  = tid >> 4;   // n: ty*4+i

    __shared__ __align__(16) float sm[64 * 132];   // 33.8 KB; tiles use 24 KB
    float4*     as4   = reinterpret_cast<float4*>(sm);            // [8 q][128 m]
    float4*     xs4   = reinterpret_cast<float4*>(sm + 4096);     // [8 q][64 n]
    ulonglong2* as4u  = reinterpret_cast<ulonglong2*>(sm);
    ulonglong2* xs4u  = reinterpret_cast<ulonglong2*>(sm + 4096);

    const float* Ab = A + (size_t)c * MM * FF;

    // precompute swizzled lane offsets: a-side tx^q, x-side (ty*4)^(q&4)
    int txq[8];
#pragma unroll
    for (int q = 0; q < 8; q++) txq[q] = tx ^ q;
    int tyq[2];
    tyq[0] = ty * 4;
    tyq[1] = (ty * 4) ^ 4;

    u64 acc[4][8];
#pragma unroll
    for (int i = 0; i < 4; i++)
#pragma unroll
        for (int j = 0; j < 8; j++) acc[i][j] = 0ull;

    float4 ra[4], rx[2];
    // prefetch chunk 0
#pragma unroll
    for (int it = 0; it < 4; it++) {
        int idx = it * 256 + tid, m = idx >> 3, q = idx & 7;
        ra[it] = *reinterpret_cast<const float4*>(Ab + (size_t)m * FF + q * 4);
    }
#pragma unroll
    for (int it = 0; it < 2; it++) {
        int idx = it * 256 + tid, n = idx >> 3, q = idx & 7;
        rx[it] = *reinterpret_cast<const float4*>(X + ((size_t)n * CC + c) * FF + q * 4);
    }

    for (int ch = 0; ch < 64; ch++) {
        // stage registers -> smem (swizzle: column index XOR q)
#pragma unroll
        for (int it = 0; it < 4; it++) {
            int idx = it * 256 + tid, m = idx >> 3, q = idx & 7;
            as4[q * 128 + (m ^ q)] = ra[it];
        }
#pragma unroll
        for (int it = 0; it < 2; it++) {
            int idx = it * 256 + tid, n = idx >> 3, q = idx & 7;
            xs4[q * 64 + (n ^ q)] = rx[it];
        }
        __syncthreads();

        if (ch < 63) {  // prefetch next chunk during compute
            const int k0 = (ch + 1) * 32;
#pragma unroll
            for (int it = 0; it < 4; it++) {
                int idx = it * 256 + tid, m = idx >> 3, q = idx & 7;
                ra[it] = *reinterpret_cast<const float4*>(Ab + (size_t)m * FF + k0 + q * 4);
            }
#pragma unroll
            for (int it = 0; it < 2; it++) {
                int idx = it * 256 + tid, n = idx >> 3, q = idx & 7;
                rx[it] = *reinterpret_cast<const float4*>(X + ((size_t)n * CC + c) * FF + k0 + q * 4);
            }
        }

#pragma unroll
        for (int q = 0; q < 8; q++) {
            // read addresses: all XOR terms are immediates or precomputed regs
            ulonglong2 x2[4], a2[8];
#pragma unroll
            for (int i = 0; i < 4; i++)
                x2[i] = xs4u[q * 64 + tyq[(q >> 2) & 1] + (i ^ (q & 3))];
#pragma unroll
            for (int j = 0; j < 8; j++)
                a2[j] = as4u[q * 128 + j * 16 + txq[q]];
#pragma unroll
            for (int i = 0; i < 4; i++)
#pragma unroll
                for (int j = 0; j < 8; j++) {
                    acc[i][j] = ffma2(x2[i].x, a2[j].x, acc[i][j]);
                    acc[i][j] = ffma2(x2[i].y, a2[j].y, acc[i][j]);
                }
        }
        __syncthreads();
    }

    // epilogue: reduce pair halves, stash scores, softmax over m, write g_W
    float* Ss = sm;  // [64][132]
#pragma unroll
    for (int i = 0; i < 4; i++) {
        int n = ty * 4 + i;
#pragma unroll
        for (int j = 0; j < 8; j++) {
            float2 v = unpack2(acc[i][j]);
            Ss[n * 132 + (j * 16 + tx)] = v.x + v.y;
        }
    }
    __syncthreads();

    if (tid < 64) {
        float* row = Ss + tid * 132;
        float mx = row[0];
#pragma unroll 8
        for (int m = 1; m < 128; m++) mx = fmaxf(mx, row[m]);
        float sum = 0.f;
#pragma unroll 8
        for (int m = 0; m < 128; m++) {
            float e = __expf(row[m] - mx);
            sum += e;
            row[m] = e;
        }
        float inv = 1.f / sum;
        float4* w4 = reinterpret_cast<float4*>(g_W + ((size_t)tid * CC + c) * MM);
#pragma unroll 8
        for (int m4 = 0; m4 < 32; m4++) {
            w4[m4] = make_float4(row[m4 * 4 + 0] * inv, row[m4 * 4 + 1] * inv,
                                 row[m4 * 4 + 2] * inv, row[m4 * 4 + 3] * inv);
        }
    }
}

// ============================================================================
// Kernel 2: out[n,c,f] = sum_m W[n,c,m]*X[n,m,f]. Grid (16 f-tiles, 64 n).
// Tile 128c x 128f, K=m chunked by 32.
// Wt smem [m][c] pitch 132 (16B-aligned rows). W staged with c on the lane
// index -> conflict-free transpose stores; reads are 2 broadcast LDS.128/k.
// Xs [m][f] natural, reads 2 LDS.128/k. Thread tile 8c x 8f (f32x2 f-pairs).
// ============================================================================
__global__ __launch_bounds__(256, 2) void k2_combine(const float* __restrict__ X,
                                                     float* __restrict__ Out) {
    const int n   = blockIdx.y;
    const int f0  = blockIdx.x * 128;
    const int tid = threadIdx.x;
    const int tx  = tid & 15;   // f (float4 column)
    const int ty  = tid >> 4;   // c group

    __shared__ __align__(16) float Wt[32 * 132];  // [m][c], pitch 132 floats
    __shared__ __align__(16) float Xs[32 * 128];  // [m][f]
    float4*     Wt4  = reinterpret_cast<float4*>(Wt);  // pitch 33 float4
    float4*     Xs4  = reinterpret_cast<float4*>(Xs);  // pitch 32 float4
    ulonglong2* Xs4u = reinterpret_cast<ulonglong2*>(Xs);

    const float* Wg = g_W + (size_t)n * CC * MM;
    const float* Xb = X + (size_t)n * CC * FF + f0;

    ulonglong2 acc2[8][2];
#pragma unroll
    for (int i = 0; i < 8; i++)
#pragma unroll
        for (int h = 0; h < 2; h++) acc2[i][h] = make_ulonglong2(0ull, 0ull);

    float4 rw[4], rx[4];
    // prefetch chunk 0: W with c on the lane index (strided global, L2-hot)
#pragma unroll
    for (int it = 0; it < 4; it++) {
        int idx = it * 256 + tid, cc = idx & 127, q = idx >> 7;
        rw[it] = *reinterpret_cast<const float4*>(Wg + (size_t)cc * MM + q * 4);
    }
#pragma unroll
    for (int it = 0; it < 4; it++) {
        int idx = it * 256 + tid, ml = idx >> 5, fq = idx & 31;
        rx[it] = *reinterpret_cast<const float4*>(Xb + (size_t)ml * FF + fq * 4);
    }

    for (int ch = 0; ch < 4; ch++) {
#pragma unroll
        for (int it = 0; it < 4; it++) {
            int idx = it * 256 + tid, cc = idx & 127, q = idx >> 7;
            Wt[(q * 4 + 0) * 132 + cc] = rw[it].x;   // lanes: cc consecutive
            Wt[(q * 4 + 1) * 132 + cc] = rw[it].y;   // -> conflict-free
            Wt[(q * 4 + 2) * 132 + cc] = rw[it].z;
            Wt[(q * 4 + 3) * 132 + cc] = rw[it].w;
        }
#pragma unroll
        for (int it = 0; it < 4; it++) {
            int idx = it * 256 + tid, ml = idx >> 5, fq = idx & 31;
            Xs4[ml * 32 + fq] = rx[it];
        }
        __syncthreads();

        if (ch < 3) {
            const int m0 = (ch + 1) * 32;
#pragma unroll
            for (int it = 0; it < 4; it++) {
                int idx = it * 256 + tid, cc = idx & 127, q = idx >> 7;
                rw[it] = *reinterpret_cast<const float4*>(Wg + (size_t)cc * MM + m0 + q * 4);
            }
#pragma unroll
            for (int it = 0; it < 4; it++) {
                int idx = it * 256 + tid, ml = idx >> 5, fq = idx & 31;
                rx[it] = *reinterpret_cast<const float4*>(Xb + (size_t)(m0 + ml) * FF + fq * 4);
            }
        }

#pragma unroll 4
        for (int k = 0; k < 32; k++) {
            float4 w40 = Wt4[k * 33 + ty * 2];        // c = ty*8 .. +3 (broadcast)
            float4 w41 = Wt4[k * 33 + ty * 2 + 1];    // c = ty*8+4 .. +7
            ulonglong2 xa = Xs4u[k * 32 + tx];        // f-pairs 2tx*2 ..
            ulonglong2 xb = Xs4u[k * 32 + 16 + tx];
            u64 wd[8];
            wd[0] = pack2(w40.x, w40.x); wd[1] = pack2(w40.y, w40.y);
            wd[2] = pack2(w40.z, w40.z); wd[3] = pack2(w40.w, w40.w);
            wd[4] = pack2(w41.x, w41.x); wd[5] = pack2(w41.y, w41.y);
            wd[6] = pack2(w41.z, w41.z); wd[7] = pack2(w41.w, w41.w);
#pragma unroll
            for (int ci = 0; ci < 8; ci++) {
                acc2[ci][0].x = ffma2(wd[ci], xa.x, acc2[ci][0].x);
                acc2[ci][0].y = ffma2(wd[ci], xa.y, acc2[ci][0].y);
                acc2[ci][1].x = ffma2(wd[ci], xb.x, acc2[ci][1].x);
                acc2[ci][1].y = ffma2(wd[ci], xb.y, acc2[ci][1].y);
            }
        }
        __syncthreads();
    }

    // store: thread owns c = ty*8+ci; float4 columns h*16+tx (same map as Xs)
#pragma unroll
    for (int ci = 0; ci < 8; ci++) {
        int c = ty * 8 + ci;
        float4* O4 = reinterpret_cast<float4*>(Out + ((size_t)n * CC + c) * FF + f0);
        O4[tx]      = *reinterpret_cast<float4*>(&acc2[ci][0]);
        O4[16 + tx] = *reinterpret_cast<float4*>(&acc2[ci][1]);
    }
}

extern "C" void kernel_launch(void* const* d_in, const int* in_sizes, int n_in,
                              void* d_out, int out_size) {
    const float* X = (const float*)d_in[0];
    const float* A = (const float*)d_in[1];
    float* Out = (float*)d_out;

    k1_scores<<<CC, 256>>>(X, A);
    dim3 g2(FF / 128, NN);
    k2_combine<<<g2, 256>>>(X, Out);
}

// round 8
// speedup vs baseline: 1.6825x; 1.3835x over previous
#include <cuda_runtime.h>
#include <cuda_bf16.h>
#include <cstdint>

#define NN 64
#define CC 128
#define FF 2048
#define MM 128
typedef unsigned long long u64;

__device__ __nv_bfloat16 g_Whi[(size_t)NN * CC * MM];
__device__ __nv_bfloat16 g_Wlo[(size_t)NN * CC * MM];

__device__ __forceinline__ uint32_t smem_u32(const void* p) {
    uint32_t a;
    asm("{ .reg .u64 t; cvta.to.shared.u64 t, %1; cvt.u32.u64 %0, t; }" : "=r"(a) : "l"(p));
    return a;
}
__device__ __forceinline__ void ldm_x4(uint32_t* r, uint32_t addr) {
    asm volatile("ldmatrix.sync.aligned.m8n8.x4.shared.b16 {%0,%1,%2,%3}, [%4];"
                 : "=r"(r[0]), "=r"(r[1]), "=r"(r[2]), "=r"(r[3]) : "r"(addr));
}
__device__ __forceinline__ void ldm_x4t(uint32_t* r, uint32_t addr) {
    asm volatile("ldmatrix.sync.aligned.m8n8.x4.trans.shared.b16 {%0,%1,%2,%3}, [%4];"
                 : "=r"(r[0]), "=r"(r[1]), "=r"(r[2]), "=r"(r[3]) : "r"(addr));
}
__device__ __forceinline__ void mma16816(float* d, const uint32_t* a,
                                         uint32_t b0, uint32_t b1) {
    asm volatile(
        "mma.sync.aligned.m16n8k16.row.col.f32.bf16.bf16.f32 "
        "{%0,%1,%2,%3}, {%4,%5,%6,%7}, {%8,%9}, {%0,%1,%2,%3};"
        : "+f"(d[0]), "+f"(d[1]), "+f"(d[2]), "+f"(d[3])
        : "r"(a[0]), "r"(a[1]), "r"(a[2]), "r"(a[3]), "r"(b0), "r"(b1));
}
// split f32x4 -> hi/lo bf16x4 packed in u64 (k-ascending)
__device__ __forceinline__ void cvt4(const float4 v, u64& hi, u64& lo) {
    __nv_bfloat162 h01 = __floats2bfloat162_rn(v.x, v.y);
    __nv_bfloat162 h23 = __floats2bfloat162_rn(v.z, v.w);
    float2 f01 = __bfloat1622float2(h01);
    float2 f23 = __bfloat1622float2(h23);
    __nv_bfloat162 l01 = __floats2bfloat162_rn(v.x - f01.x, v.y - f01.y);
    __nv_bfloat162 l23 = __floats2bfloat162_rn(v.z - f23.x, v.w - f23.y);
    hi = (u64)*(uint32_t*)&h01 | ((u64)*(uint32_t*)&h23 << 32);
    lo = (u64)*(uint32_t*)&l01 | ((u64)*(uint32_t*)&l23 << 32);
}

// ============================================================================
// k1: CTA per c. S[n=64, m=128] = sum_f A_c[m,f]*X[n,c,f] via split-bf16 HMMA.
// K chunks of 32. smem (33792B static, reused as Ss[64][132] for softmax):
//   Ahi @0 (128 rows x 80B), Alo @10240, Xhi @20480 (64 x 80B), Xlo @25600.
// Warp w: n-block (w&3)*16, m-block (w>>2)*64 (8 m8-tiles).
// ============================================================================
__global__ __launch_bounds__(256) void k1_scores(const float* __restrict__ X,
                                                 const float* __restrict__ A) {
    __shared__ __align__(16) char smem[33792];
    const uint32_t sB = smem_u32(smem);
    const int tid = threadIdx.x, w = tid >> 5, lane = tid & 31;
    const int c = blockIdx.x;
    const int nb = w & 3, mb = w >> 2;

    // staging maps
    const int ar = tid >> 1, ah = tid & 1;   // A: row m, k-half (16 floats)
    const int xr = tid >> 2, xq = tid & 3;   // X: row n, k-quarter (8 floats)
    const float* Arow = A + ((size_t)c * MM + ar) * FF + ah * 16;
    const float* Xrow = X + ((size_t)xr * CC + c) * FF + xq * 8;

    // ldmatrix base addresses (per-lane)
    const uint32_t xfrow = nb * 16 + (lane & 7) + ((lane >> 3) & 1) * 8;
    const uint32_t xfbase = sB + 20480 + xfrow * 80 + ((lane >> 4) & 1) * 16;
    const uint32_t afrow = mb * 64 + (lane & 7) + ((lane >> 4) & 1) * 8;
    const uint32_t afbase = sB + afrow * 80 + ((lane >> 3) & 1) * 16;

    float d[8][4];
#pragma unroll
    for (int t = 0; t < 8; t++)
#pragma unroll
        for (int i = 0; i < 4; i++) d[t][i] = 0.f;

    float4 ra[4], rx[2];
#pragma unroll
    for (int i = 0; i < 4; i++) ra[i] = *(const float4*)(Arow + i * 4);
#pragma unroll
    for (int i = 0; i < 2; i++) rx[i] = *(const float4*)(Xrow + i * 4);

    for (int ch = 0; ch < 64; ch++) {
        // stage regs -> smem (split hi/lo)
#pragma unroll
        for (int i = 0; i < 4; i++) {
            u64 hi, lo; cvt4(ra[i], hi, lo);
            const uint32_t o = (uint32_t)(ar * 80 + ah * 32 + i * 8);
            *(u64*)(smem + o) = hi;  *(u64*)(smem + 10240 + o) = lo;
        }
#pragma unroll
        for (int i = 0; i < 2; i++) {
            u64 hi, lo; cvt4(rx[i], hi, lo);
            const uint32_t o = (uint32_t)(xr * 80 + xq * 16 + i * 8);
            *(u64*)(smem + 20480 + o) = hi;  *(u64*)(smem + 25600 + o) = lo;
        }
        __syncthreads();
        if (ch < 63) {  // prefetch next chunk; LDG latency hidden by HMMA below
            const int k0 = (ch + 1) * 32;
#pragma unroll
            for (int i = 0; i < 4; i++) ra[i] = *(const float4*)(Arow + k0 + i * 4);
#pragma unroll
            for (int i = 0; i < 2; i++) rx[i] = *(const float4*)(Xrow + k0 + i * 4);
        }
#pragma unroll
        for (int ks = 0; ks < 2; ks++) {
            uint32_t xh[4], xl[4], ahf[16], alf[16];
            ldm_x4(xh, xfbase + ks * 32);
            ldm_x4(xl, xfbase + 5120 + ks * 32);
#pragma unroll
            for (int p = 0; p < 4; p++) ldm_x4(ahf + p * 4, afbase + p * 1280 + ks * 32);
#pragma unroll
            for (int p = 0; p < 4; p++) ldm_x4(alf + p * 4, afbase + 10240 + p * 1280 + ks * 32);
#pragma unroll
            for (int t = 0; t < 8; t++) mma16816(d[t], xh, ahf[t * 2], ahf[t * 2 + 1]);
#pragma unroll
            for (int t = 0; t < 8; t++) mma16816(d[t], xh, alf[t * 2], alf[t * 2 + 1]);
#pragma unroll
            for (int t = 0; t < 8; t++) mma16816(d[t], xl, ahf[t * 2], ahf[t * 2 + 1]);
        }
        __syncthreads();
    }

    // D frags -> Ss[n][m] (pitch 132), softmax over m, split-write Whi/Wlo
    float* Ss = (float*)smem;
    const int r0 = nb * 16 + (lane >> 2);
#pragma unroll
    for (int t = 0; t < 8; t++) {
        const int mcol = mb * 64 + t * 8 + (lane & 3) * 2;
        Ss[r0 * 132 + mcol]           = d[t][0];
        Ss[r0 * 132 + mcol + 1]       = d[t][1];
        Ss[(r0 + 8) * 132 + mcol]     = d[t][2];
        Ss[(r0 + 8) * 132 + mcol + 1] = d[t][3];
    }
    __syncthreads();
    if (tid < 64) {
        float* row = Ss + tid * 132;
        float mx = row[0];
#pragma unroll 8
        for (int m = 1; m < 128; m++) mx = fmaxf(mx, row[m]);
        float sum = 0.f;
#pragma unroll 8
        for (int m = 0; m < 128; m++) { float e = __expf(row[m] - mx); sum += e; row[m] = e; }
        const float inv = 1.f / sum;
        __nv_bfloat16* whi = g_Whi + ((size_t)tid * CC + c) * MM;
        __nv_bfloat16* wlo = g_Wlo + ((size_t)tid * CC + c) * MM;
#pragma unroll 4
        for (int m = 0; m < 128; m += 2) {
            float w0 = row[m] * inv, w1 = row[m + 1] * inv;
            __nv_bfloat162 h = __floats2bfloat162_rn(w0, w1);
            float2 hf = __bfloat1622float2(h);
            __nv_bfloat162 l = __floats2bfloat162_rn(w0 - hf.x, w1 - hf.y);
            *(__nv_bfloat162*)(whi + m) = h;
            *(__nv_bfloat162*)(wlo + m) = l;
        }
    }
}

// ============================================================================
// k2: grid (2 f-halves, 64 n). out[c=128, f] = sum_m W[n,c,m]*X[n,m,f].
// W resident smem K-major (pitch 272B): Whi @0, Wlo @34816.
// X tile [m=128][f=64] (pitch 144B): Xhi @69632, Xlo @88064. Total 106496B.
// Warp w owns c-block w*16; B-op via ldmatrix.x4.trans (X f-contiguous).
// 16 f-tiles of 64; register prefetch of next tile overlaps HMMA.
// ============================================================================
__global__ __launch_bounds__(256) void k2_combine(const float* __restrict__ X,
                                                  float* __restrict__ Out) {
    extern __shared__ __align__(16) char sm2[];
    const uint32_t sB = smem_u32(sm2);
    const int tid = threadIdx.x, w = tid >> 5, lane = tid & 31;
    const int n = blockIdx.y, fh = blockIdx.x;

    const int cr = tid >> 1, hh = tid & 1;
    {   // stage W hi/lo (resident for whole kernel)
        const __nv_bfloat16* WhiG = g_Whi + ((size_t)n * CC + cr) * MM + hh * 64;
        const __nv_bfloat16* WloG = g_Wlo + ((size_t)n * CC + cr) * MM + hh * 64;
#pragma unroll
        for (int i = 0; i < 16; i++) {
            const uint32_t o = (uint32_t)(cr * 272 + hh * 128 + i * 8);
            *(u64*)(sm2 + o)         = *(const u64*)(WhiG + i * 4);
            *(u64*)(sm2 + 34816 + o) = *(const u64*)(WloG + i * 4);
        }
    }

    // frag bases
    const uint32_t wrow = w * 16 + (lane & 7) + ((lane >> 3) & 1) * 8;
    const uint32_t wbase = sB + wrow * 272 + ((lane >> 4) & 1) * 16;
    const uint32_t xmrow = (lane & 7) + ((lane >> 3) & 1) * 8;
    const uint32_t xbase = sB + 69632 + xmrow * 144 + ((lane >> 4) & 1) * 16;

    const float* Xrow2 = X + ((size_t)n * CC + cr) * FF + fh * 1024 + hh * 32;
    float* Ob = Out + ((size_t)n * CC) * FF + fh * 1024;

    float4 rx[8];
#pragma unroll
    for (int i = 0; i < 8; i++) rx[i] = *(const float4*)(Xrow2 + i * 4);
    __syncthreads();   // W staged

    for (int t = 0; t < 16; t++) {
        // stage X tile (split hi/lo)
#pragma unroll
        for (int i = 0; i < 8; i++) {
            u64 hi, lo; cvt4(rx[i], hi, lo);
            const uint32_t o = (uint32_t)(cr * 144 + hh * 64 + i * 8);
            *(u64*)(sm2 + 69632 + o) = hi;  *(u64*)(sm2 + 88064 + o) = lo;
        }
        __syncthreads();
        if (t < 15) {
#pragma unroll
            for (int i = 0; i < 8; i++)
                rx[i] = *(const float4*)(Xrow2 + (t + 1) * 64 + i * 4);
        }

        float d[8][4];
#pragma unroll
        for (int ft = 0; ft < 8; ft++)
#pragma unroll
            for (int i = 0; i < 4; i++) d[ft][i] = 0.f;

#pragma unroll
        for (int ks = 0; ks < 8; ks++) {
            uint32_t whf[4], wlf[4], xh[16], xl[16];
            ldm_x4(whf, wbase + ks * 32);
            ldm_x4(wlf, wbase + 34816 + ks * 32);
#pragma unroll
            for (int j = 0; j < 4; j++) ldm_x4t(xh + j * 4, xbase + ks * 2304 + j * 32);
#pragma unroll
            for (int j = 0; j < 4; j++) ldm_x4t(xl + j * 4, xbase + 18432 + ks * 2304 + j * 32);
#pragma unroll
            for (int ft = 0; ft < 8; ft++) mma16816(d[ft], whf, xh[ft * 2], xh[ft * 2 + 1]);
#pragma unroll
            for (int ft = 0; ft < 8; ft++) mma16816(d[ft], whf, xl[ft * 2], xl[ft * 2 + 1]);
#pragma unroll
            for (int ft = 0; ft < 8; ft++) mma16816(d[ft], wlf, xh[ft * 2], xh[ft * 2 + 1]);
        }

        // store: rows c = w*16 + lane>>2 (+8), f = t*64 + ft*8 + (lane&3)*2
        const int crow = w * 16 + (lane >> 2);
#pragma unroll
        for (int ft = 0; ft < 8; ft++) {
            const int f = t * 64 + ft * 8 + (lane & 3) * 2;
            *(float2*)(Ob + (size_t)crow * FF + f)       = make_float2(d[ft][0], d[ft][1]);
            *(float2*)(Ob + (size_t)(crow + 8) * FF + f) = make_float2(d[ft][2], d[ft][3]);
        }
        __syncthreads();
    }
}

extern "C" void kernel_launch(void* const* d_in, const int* in_sizes, int n_in,
                              void* d_out, int out_size) {
    const float* X = (const float*)d_in[0];
    const float* A = (const float*)d_in[1];
    float* Out = (float*)d_out;

    cudaFuncSetAttribute(k2_combine, cudaFuncAttributeMaxDynamicSharedMemorySize, 106496);

    k1_scores<<<CC, 256>>>(X, A);
    dim3 g2(2, NN);
    k2_combine<<<g2, 256, 106496>>>(X, Out);
}

// round 9
// speedup vs baseline: 1.8937x; 1.1255x over previous
#include <cuda_runtime.h>
#include <cuda_bf16.h>
#include <cstdint>

#define NN 64
#define CC 128
#define FF 2048
#define MM 128
typedef unsigned long long u64;

__device__ __nv_bfloat16 g_Whi[(size_t)NN * CC * MM];
__device__ __nv_bfloat16 g_Wlo[(size_t)NN * CC * MM];

__device__ __forceinline__ uint32_t smem_u32(const void* p) {
    uint32_t a;
    asm("{ .reg .u64 t; cvta.to.shared.u64 t, %1; cvt.u32.u64 %0, t; }" : "=r"(a) : "l"(p));
    return a;
}
__device__ __forceinline__ void ldm_x4(uint32_t* r, uint32_t addr) {
    asm volatile("ldmatrix.sync.aligned.m8n8.x4.shared.b16 {%0,%1,%2,%3}, [%4];"
                 : "=r"(r[0]), "=r"(r[1]), "=r"(r[2]), "=r"(r[3]) : "r"(addr));
}
__device__ __forceinline__ void ldm_x4t(uint32_t* r, uint32_t addr) {
    asm volatile("ldmatrix.sync.aligned.m8n8.x4.trans.shared.b16 {%0,%1,%2,%3}, [%4];"
                 : "=r"(r[0]), "=r"(r[1]), "=r"(r[2]), "=r"(r[3]) : "r"(addr));
}
__device__ __forceinline__ void mma16816(float* d, const uint32_t* a,
                                         uint32_t b0, uint32_t b1) {
    asm volatile(
        "mma.sync.aligned.m16n8k16.row.col.f32.bf16.bf16.f32 "
        "{%0,%1,%2,%3}, {%4,%5,%6,%7}, {%8,%9}, {%0,%1,%2,%3};"
        : "+f"(d[0]), "+f"(d[1]), "+f"(d[2]), "+f"(d[3])
        : "r"(a[0]), "r"(a[1]), "r"(a[2]), "r"(a[3]), "r"(b0), "r"(b1));
}
__device__ __forceinline__ void cvt4(const float4 v, u64& hi, u64& lo) {
    __nv_bfloat162 h01 = __floats2bfloat162_rn(v.x, v.y);
    __nv_bfloat162 h23 = __floats2bfloat162_rn(v.z, v.w);
    float2 f01 = __bfloat1622float2(h01);
    float2 f23 = __bfloat1622float2(h23);
    __nv_bfloat162 l01 = __floats2bfloat162_rn(v.x - f01.x, v.y - f01.y);
    __nv_bfloat162 l23 = __floats2bfloat162_rn(v.z - f23.x, v.w - f23.y);
    hi = (u64)*(uint32_t*)&h01 | ((u64)*(uint32_t*)&h23 << 32);
    lo = (u64)*(uint32_t*)&l01 | ((u64)*(uint32_t*)&l23 << 32);
}

// ============================================================================
// k1: CTA per c. S[64n,128m] = sum_f A_c[m,f]*X[n,c,f], split-bf16 HMMA,
// K chunks of 64, DOUBLE-BUFFERED (1 sync/chunk). Fused softmax (4 thr/row).
// Buffer (55296B, pitch 144): Ahi@0 Alo@18432 Xhi@36864 Xlo@46080.
// smem = 2 buffers = 110592B dynamic; epilogue Ss[64][132] reuses buf0.
// ============================================================================
__global__ __launch_bounds__(256, 1) void k1_scores(const float* __restrict__ X,
                                                    const float* __restrict__ A) {
    extern __shared__ __align__(16) char sm1[];
    const uint32_t sB = smem_u32(sm1);
    const int tid = threadIdx.x, w = tid >> 5, lane = tid & 31;
    const int c = blockIdx.x;
    const int nb = w & 3, mb = w >> 2;

    const int ar = tid >> 1, ah = tid & 1;   // A: row m, 32-float half of 64k
    const int xr = tid >> 2, xq = tid & 3;   // X: row n, 16-float quarter
    const float* Arow = A + ((size_t)c * MM + ar) * FF + ah * 32;
    const float* Xrow = X + ((size_t)xr * CC + c) * FF + xq * 16;

    // fragment base offsets (within a buffer)
    const uint32_t xfrow = nb * 16 + (lane & 7) + ((lane >> 3) & 1) * 8;
    const uint32_t xfoff = 36864 + xfrow * 144 + ((lane >> 4) & 1) * 16;
    const uint32_t afrow = mb * 64 + (lane & 7) + ((lane >> 4) & 1) * 8;
    const uint32_t afoff = afrow * 144 + ((lane >> 3) & 1) * 16;

    float d[8][4];
#pragma unroll
    for (int t = 0; t < 8; t++)
#pragma unroll
        for (int i = 0; i < 4; i++) d[t][i] = 0.f;

    float4 ra[8], rx[4];
    // chunk 0 -> regs -> buf0
#pragma unroll
    for (int i = 0; i < 8; i++) ra[i] = *(const float4*)(Arow + i * 4);
#pragma unroll
    for (int i = 0; i < 4; i++) rx[i] = *(const float4*)(Xrow + i * 4);
#pragma unroll
    for (int i = 0; i < 8; i++) {
        u64 hi, lo; cvt4(ra[i], hi, lo);
        const uint32_t o = (uint32_t)(ar * 144 + ah * 64 + i * 8);
        *(u64*)(sm1 + o) = hi;  *(u64*)(sm1 + 18432 + o) = lo;
    }
#pragma unroll
    for (int i = 0; i < 4; i++) {
        u64 hi, lo; cvt4(rx[i], hi, lo);
        const uint32_t o = (uint32_t)(xr * 144 + xq * 32 + i * 8);
        *(u64*)(sm1 + 36864 + o) = hi;  *(u64*)(sm1 + 46080 + o) = lo;
    }
    // chunk 1 -> regs
#pragma unroll
    for (int i = 0; i < 8; i++) ra[i] = *(const float4*)(Arow + 64 + i * 4);
#pragma unroll
    for (int i = 0; i < 4; i++) rx[i] = *(const float4*)(Xrow + 64 + i * 4);
    __syncthreads();

    for (int ch = 0; ch < 32; ch++) {
        const int b = ch & 1;
        char* nbuf = sm1 + (b ^ 1) * 55296;
        // stage chunk ch+1 (regs) into the other buffer (overlaps compute below)
        if (ch < 31) {
#pragma unroll
            for (int i = 0; i < 8; i++) {
                u64 hi, lo; cvt4(ra[i], hi, lo);
                const uint32_t o = (uint32_t)(ar * 144 + ah * 64 + i * 8);
                *(u64*)(nbuf + o) = hi;  *(u64*)(nbuf + 18432 + o) = lo;
            }
#pragma unroll
            for (int i = 0; i < 4; i++) {
                u64 hi, lo; cvt4(rx[i], hi, lo);
                const uint32_t o = (uint32_t)(xr * 144 + xq * 32 + i * 8);
                *(u64*)(nbuf + 36864 + o) = hi;  *(u64*)(nbuf + 46080 + o) = lo;
            }
        }
        if (ch < 30) {   // LDG chunk ch+2
            const int k0 = (ch + 2) * 64;
#pragma unroll
            for (int i = 0; i < 8; i++) ra[i] = *(const float4*)(Arow + k0 + i * 4);
#pragma unroll
            for (int i = 0; i < 4; i++) rx[i] = *(const float4*)(Xrow + k0 + i * 4);
        }
        // compute buffer b
        const uint32_t B = sB + b * 55296;
#pragma unroll
        for (int ks = 0; ks < 4; ks++) {
            uint32_t xh[4], xl[4], ahf[16], alf[16];
            ldm_x4(xh, B + xfoff + ks * 32);
            ldm_x4(xl, B + xfoff + 9216 + ks * 32);
#pragma unroll
            for (int p = 0; p < 4; p++) ldm_x4(ahf + p * 4, B + afoff + p * 2304 + ks * 32);
#pragma unroll
            for (int p = 0; p < 4; p++) ldm_x4(alf + p * 4, B + afoff + 18432 + p * 2304 + ks * 32);
#pragma unroll
            for (int t = 0; t < 8; t++) mma16816(d[t], xh, ahf[t * 2], ahf[t * 2 + 1]);
#pragma unroll
            for (int t = 0; t < 8; t++) mma16816(d[t], xh, alf[t * 2], alf[t * 2 + 1]);
#pragma unroll
            for (int t = 0; t < 8; t++) mma16816(d[t], xl, ahf[t * 2], ahf[t * 2 + 1]);
        }
        __syncthreads();
    }

    // scores -> Ss[n][m] (pitch 132 floats, reuses buf0)
    float* Ss = (float*)sm1;
    const int r0 = nb * 16 + (lane >> 2);
#pragma unroll
    for (int t = 0; t < 8; t++) {
        const int mcol = mb * 64 + t * 8 + (lane & 3) * 2;
        Ss[r0 * 132 + mcol]           = d[t][0];
        Ss[r0 * 132 + mcol + 1]       = d[t][1];
        Ss[(r0 + 8) * 132 + mcol]     = d[t][2];
        Ss[(r0 + 8) * 132 + mcol + 1] = d[t][3];
    }
    __syncthreads();

    // softmax: 4 threads per row, shfl-combined
    {
        const int row = tid >> 2, q = tid & 3;
        float* Rs = Ss + row * 132 + q * 32;
        float mx = Rs[0];
#pragma unroll 8
        for (int m = 1; m < 32; m++) mx = fmaxf(mx, Rs[m]);
        mx = fmaxf(mx, __shfl_xor_sync(0xffffffffu, mx, 1));
        mx = fmaxf(mx, __shfl_xor_sync(0xffffffffu, mx, 2));
        float sum = 0.f;
#pragma unroll 8
        for (int m = 0; m < 32; m++) { float e = __expf(Rs[m] - mx); sum += e; Rs[m] = e; }
        sum += __shfl_xor_sync(0xffffffffu, sum, 1);
        sum += __shfl_xor_sync(0xffffffffu, sum, 2);
        const float inv = 1.f / sum;
        __nv_bfloat16* whi = g_Whi + ((size_t)row * CC + c) * MM + q * 32;
        __nv_bfloat16* wlo = g_Wlo + ((size_t)row * CC + c) * MM + q * 32;
#pragma unroll 4
        for (int m = 0; m < 32; m += 2) {
            float w0 = Rs[m] * inv, w1 = Rs[m + 1] * inv;
            __nv_bfloat162 h = __floats2bfloat162_rn(w0, w1);
            float2 hf = __bfloat1622float2(h);
            __nv_bfloat162 l = __floats2bfloat162_rn(w0 - hf.x, w1 - hf.y);
            *(__nv_bfloat162*)(whi + m) = h;
            *(__nv_bfloat162*)(wlo + m) = l;
        }
    }
}

// ============================================================================
// k2: grid (2 f-halves, 64 n). out[c,f] = sum_m W[n,c,m]*X[n,m,f].
// W fragments preloaded to REGISTERS (64 regs/thread) via one-time smem stage.
// X tiles [m=128][f=64] double-buffered (pitch 144): buf b @ b*36864,
// hi @0, lo @18432. Dynamic smem = 73728 (W stage 69632 reuses same space).
// One sync per tile; stage(t+1) + LDG(t+2) overlap compute(t).
// ============================================================================
__global__ __launch_bounds__(256, 1) void k2_combine(const float* __restrict__ X,
                                                     float* __restrict__ Out) {
    extern __shared__ __align__(16) char sm2[];
    const uint32_t sB = smem_u32(sm2);
    const int tid = threadIdx.x, w = tid >> 5, lane = tid & 31;
    const int n = blockIdx.y, fh = blockIdx.x;

    const int cr = tid >> 1, hh = tid & 1;
    // ---- one-time W stage (pitch 272) + fragment preload to registers ----
    {
        const __nv_bfloat16* WhiG = g_Whi + ((size_t)n * CC + cr) * MM + hh * 64;
        const __nv_bfloat16* WloG = g_Wlo + ((size_t)n * CC + cr) * MM + hh * 64;
#pragma unroll
        for (int i = 0; i < 16; i++) {
            const uint32_t o = (uint32_t)(cr * 272 + hh * 128 + i * 8);
            *(u64*)(sm2 + o)         = *(const u64*)(WhiG + i * 4);
            *(u64*)(sm2 + 34816 + o) = *(const u64*)(WloG + i * 4);
        }
    }
    __syncthreads();
    uint32_t wh[32], wl[32];
    {
        const uint32_t wrow = w * 16 + (lane & 7) + ((lane >> 3) & 1) * 8;
        const uint32_t wboff = wrow * 272 + ((lane >> 4) & 1) * 16;
#pragma unroll
        for (int ks = 0; ks < 8; ks++) {
            ldm_x4(wh + ks * 4, sB + wboff + ks * 32);
            ldm_x4(wl + ks * 4, sB + 34816 + wboff + ks * 32);
        }
    }
    __syncthreads();   // W regs loaded; smem now free for X buffers

    const uint32_t xmrow = (lane & 7) + ((lane >> 3) & 1) * 8;
    const uint32_t xboff = xmrow * 144 + ((lane >> 4) & 1) * 16;
    const float* Xrow2 = X + ((size_t)n * CC + cr) * FF + fh * 1024 + hh * 32;
    float* Ob = Out + ((size_t)n * CC) * FF + fh * 1024;

    float4 rx[8];
    // tile 0 -> regs -> buf0
#pragma unroll
    for (int i = 0; i < 8; i++) rx[i] = *(const float4*)(Xrow2 + i * 4);
#pragma unroll
    for (int i = 0; i < 8; i++) {
        u64 hi, lo; cvt4(rx[i], hi, lo);
        const uint32_t o = (uint32_t)(cr * 144 + hh * 64 + i * 8);
        *(u64*)(sm2 + o) = hi;  *(u64*)(sm2 + 18432 + o) = lo;
    }
    // tile 1 -> regs
#pragma unroll
    for (int i = 0; i < 8; i++) rx[i] = *(const float4*)(Xrow2 + 64 + i * 4);
    __syncthreads();

    for (int t = 0; t < 16; t++) {
        const int b = t & 1;
        char* nbuf = sm2 + (b ^ 1) * 36864;
        if (t < 15) {   // stage tile t+1 into other buffer
#pragma unroll
            for (int i = 0; i < 8; i++) {
                u64 hi, lo; cvt4(rx[i], hi, lo);
                const uint32_t o = (uint32_t)(cr * 144 + hh * 64 + i * 8);
                *(u64*)(nbuf + o) = hi;  *(u64*)(nbuf + 18432 + o) = lo;
            }
        }
        if (t < 14) {   // LDG tile t+2
#pragma unroll
            for (int i = 0; i < 8; i++)
                rx[i] = *(const float4*)(Xrow2 + (t + 2) * 64 + i * 4);
        }

        float d[8][4];
#pragma unroll
        for (int ft = 0; ft < 8; ft++)
#pragma unroll
            for (int i = 0; i < 4; i++) d[ft][i] = 0.f;

        const uint32_t B = sB + b * 36864;
#pragma unroll
        for (int ks = 0; ks < 8; ks++) {
            uint32_t xh[16], xl[16];
#pragma unroll
            for (int j = 0; j < 4; j++) ldm_x4t(xh + j * 4, B + xboff + ks * 2304 + j * 32);
#pragma unroll
            for (int j = 0; j < 4; j++) ldm_x4t(xl + j * 4, B + xboff + 18432 + ks * 2304 + j * 32);
#pragma unroll
            for (int ft = 0; ft < 8; ft++) mma16816(d[ft], wh + ks * 4, xh[ft * 2], xh[ft * 2 + 1]);
#pragma unroll
            for (int ft = 0; ft < 8; ft++) mma16816(d[ft], wh + ks * 4, xl[ft * 2], xl[ft * 2 + 1]);
#pragma unroll
            for (int ft = 0; ft < 8; ft++) mma16816(d[ft], wl + ks * 4, xh[ft * 2], xh[ft * 2 + 1]);
        }

        const int crow = w * 16 + (lane >> 2);
#pragma unroll
        for (int ft = 0; ft < 8; ft++) {
            const int f = t * 64 + ft * 8 + (lane & 3) * 2;
            *(float2*)(Ob + (size_t)crow * FF + f)       = make_float2(d[ft][0], d[ft][1]);
            *(float2*)(Ob + (size_t)(crow + 8) * FF + f) = make_float2(d[ft][2], d[ft][3]);
        }
        __syncthreads();
    }
}

extern "C" void kernel_launch(void* const* d_in, const int* in_sizes, int n_in,
                              void* d_out, int out_size) {
    const float* X = (const float*)d_in[0];
    const float* A = (const float*)d_in[1];
    float* Out = (float*)d_out;

    cudaFuncSetAttribute(k1_scores, cudaFuncAttributeMaxDynamicSharedMemorySize, 110592);
    cudaFuncSetAttribute(k2_combine, cudaFuncAttributeMaxDynamicSharedMemorySize, 73728);

    k1_scores<<<CC, 256, 110592>>>(X, A);
    dim3 g2(2, NN);
    k2_combine<<<g2, 256, 73728>>>(X, Out);
}